// round 14
// baseline (speedup 1.0000x reference)
#include <cuda_runtime.h>
#include <cuda_fp16.h>
#include <cstdint>
#include <math.h>

#define B_  4
#define N_  2048
#define D_  1024
#define H_  16
#define DH_ 64

// Scratch: projected Q/K/V in [B*H][N][dh] layout, attention output X in [B*N][D]
__device__ float g_Q[B_ * H_ * N_ * DH_];
__device__ float g_K[B_ * H_ * N_ * DH_];
__device__ float g_V[B_ * H_ * N_ * DH_];
__device__ float g_X[B_ * N_ * D_];

__device__ __forceinline__ float ex2f(float x) {
    float y;
    asm("ex2.approx.ftz.f32 %0, %1;" : "=f"(y) : "f"(x));
    return y;
}
// pack two f32 -> f16x2 (lo = x, hi = y), round-to-nearest
__device__ __forceinline__ uint32_t h2pack(float x, float y) {
    uint32_t r;
    asm("cvt.rn.f16x2.f32 %0, %1, %2;" : "=r"(r) : "f"(y), "f"(x));
    return r;
}

__device__ __forceinline__ void mma_f16_16x8x16(
    float& c0, float& c1, float& c2, float& c3,
    uint32_t a0, uint32_t a1, uint32_t a2, uint32_t a3,
    uint32_t b0, uint32_t b1)
{
    asm volatile(
        "mma.sync.aligned.m16n8k16.row.col.f32.f16.f16.f32 "
        "{%0,%1,%2,%3}, {%4,%5,%6,%7}, {%8,%9}, {%0,%1,%2,%3};"
        : "+f"(c0), "+f"(c1), "+f"(c2), "+f"(c3)
        : "r"(a0), "r"(a1), "r"(a2), "r"(a3), "r"(b0), "r"(b1));
}

// ===========================================================================
// fp16 mma.sync GEMM: C[M,1024] = A[M,1024] @ W^T (+bias f32), W [N][K].
// CTA tile 128x128, k-tile 64 (= 4 k16-blocks; half the sync/LDG windows of
// the k32 version). 8 warps (4m x 2n), warp tile 32x64.
// Smem: half2-along-k, [row][KP=36 uint32] (32 data + 4 pad):
//   fragment reads rows g -> banks (36g+..) mod 32 = 4g+.. all distinct;
//   each 16-lane STS.64 phase writes one full 128B row = exact bank coverage.
// Fragment double-buffer across the 4 k16-blocks (proven pattern).
// ===========================================================================
#define KP 36   // uint32 (half2) stride per row

template <bool OUT_HEADS, bool HAS_BIAS>
__device__ __forceinline__ void gemm_mma_body(
    const float* __restrict__ A, const float* __restrict__ W,
    const float* __restrict__ bias, float* __restrict__ out)
{
    __shared__ uint32_t As[128 * KP];
    __shared__ uint32_t Bs[128 * KP];

    const int tid  = threadIdx.x;
    const int wid  = tid >> 5;
    const int lane = tid & 31;
    const int g    = lane >> 2;
    const int tig  = lane & 3;
    const int wm   = wid & 3;
    const int wn   = wid >> 2;
    const int m0   = blockIdx.y * 128;
    const int n0   = blockIdx.x * 128;

    float c[2][8][4];
#pragma unroll
    for (int t = 0; t < 2; t++)
#pragma unroll
        for (int j = 0; j < 8; j++)
#pragma unroll
            for (int e = 0; e < 4; e++) c[t][j][e] = 0.f;

    // fragment base indices
    const int ar0 = (wm * 32 + g) * KP + tig;   // + t*16*KP + kb*8 ; a1:+8*KP, a2:+4
    const int br0 = (wn * 64 + g) * KP + tig;   // + j*8*KP  + kb*8 ; b1:+4

    for (int kt = 0; kt < D_; kt += 64) {
        // Producer: 128 rows x 16 float4 cols per matrix = 2048 slots, 8/thread.
        // Each 16-lane phase covers one full row (128B) -> all 32 banks.
#pragma unroll
        for (int u = 0; u < 8; u++) {
            int f   = tid + 256 * u;
            int j   = f & 15;                    // float4 col (floats 4j..4j+3)
            int row = f >> 4;                    // 0..127
            float4 av = __ldg((const float4*)(A + (size_t)(m0 + row) * D_ + kt + j * 4));
            *(uint2*)&As[row * KP + 2 * j] =
                make_uint2(h2pack(av.x, av.y), h2pack(av.z, av.w));
            float4 wv = __ldg((const float4*)(W + (size_t)(n0 + row) * D_ + kt + j * 4));
            *(uint2*)&Bs[row * KP + 2 * j] =
                make_uint2(h2pack(wv.x, wv.y), h2pack(wv.z, wv.w));
        }
        __syncthreads();

        // Consumer: double-buffered fragments across the 4 k16-blocks.
        uint32_t a[2][2][4];   // [buf][m-tile][elem]
        uint32_t b[2][8][2];   // [buf][n-tile][elem]

        // preload k-block 0 into buf 0
#pragma unroll
        for (int t = 0; t < 2; t++) {
            int r = ar0 + t * 16 * KP;
            a[0][t][0] = As[r];
            a[0][t][1] = As[r + 8 * KP];
            a[0][t][2] = As[r + 4];
            a[0][t][3] = As[r + 8 * KP + 4];
        }
#pragma unroll
        for (int j = 0; j < 8; j++) {
            int r = br0 + j * 8 * KP;
            b[0][j][0] = Bs[r];
            b[0][j][1] = Bs[r + 4];
        }

#pragma unroll
        for (int kb = 0; kb < 4; kb++) {
            const int cur = kb & 1;
            const int nxt = cur ^ 1;
            if (kb < 3) {
                const int kk = (kb + 1) * 8;
#pragma unroll
                for (int t = 0; t < 2; t++) {
                    int r = ar0 + t * 16 * KP + kk;
                    a[nxt][t][0] = As[r];
                    a[nxt][t][1] = As[r + 8 * KP];
                    a[nxt][t][2] = As[r + 4];
                    a[nxt][t][3] = As[r + 8 * KP + 4];
                }
#pragma unroll
                for (int j = 0; j < 8; j++) {
                    int r = br0 + j * 8 * KP + kk;
                    b[nxt][j][0] = Bs[r];
                    b[nxt][j][1] = Bs[r + 4];
                }
            }
#pragma unroll
            for (int t = 0; t < 2; t++)
#pragma unroll
                for (int j = 0; j < 8; j++)
                    mma_f16_16x8x16(c[t][j][0], c[t][j][1], c[t][j][2], c[t][j][3],
                                    a[cur][t][0], a[cur][t][1], a[cur][t][2], a[cur][t][3],
                                    b[cur][j][0], b[cur][j][1]);
        }
        __syncthreads();
    }

    // Epilogue (unchanged)
#pragma unroll
    for (int t = 0; t < 2; t++) {
        const int r0 = m0 + wm * 32 + t * 16 + g;
#pragma unroll
        for (int j = 0; j < 8; j++) {
            const int col = n0 + wn * 64 + j * 8 + tig * 2;
            float2 v0 = make_float2(c[t][j][0], c[t][j][1]);
            float2 v1 = make_float2(c[t][j][2], c[t][j][3]);
            if (HAS_BIAS) {
                float2 bv = *(const float2*)(bias + col);
                v0.x += bv.x; v0.y += bv.y;
                v1.x += bv.x; v1.y += bv.y;
            }
            if (OUT_HEADS) {
                const int h = col >> 6;
                const int di = col & 63;
                const int b0i = r0 >> 11, n0i = r0 & 2047;
                const int r1 = r0 + 8;
                const int b1i = r1 >> 11, n1i = r1 & 2047;
                *(float2*)(out + (((size_t)(b0i * H_ + h)) * N_ + n0i) * DH_ + di) = v0;
                *(float2*)(out + (((size_t)(b1i * H_ + h)) * N_ + n1i) * DH_ + di) = v1;
            } else {
                *(float2*)(out + (size_t)r0 * D_ + col) = v0;
                *(float2*)(out + (size_t)(r0 + 8) * D_ + col) = v1;
            }
        }
    }
}

__global__ __launch_bounds__(256, 2)
void proj_qkv_mma(const float* __restrict__ xq, const float* __restrict__ xk,
                  const float* __restrict__ xv,
                  const float* __restrict__ Wq, const float* __restrict__ bq,
                  const float* __restrict__ Wk, const float* __restrict__ bk,
                  const float* __restrict__ Wv, const float* __restrict__ bv)
{
    int z = blockIdx.z;
    const float* A = (z == 0) ? xq : (z == 1) ? xk : xv;
    const float* W = (z == 0) ? Wq : (z == 1) ? Wk : Wv;
    const float* b = (z == 0) ? bq : (z == 1) ? bk : bv;
    float* out = (z == 0) ? g_Q : (z == 1) ? g_K : g_V;
    gemm_mma_body<true, true>(A, W, b, out);
}

__global__ __launch_bounds__(256, 2)
void proj_out_mma(const float* __restrict__ Wo, float* __restrict__ out)
{
    gemm_mma_body<false, false>(g_X, Wo, nullptr, out);
}

// ===========================================================================
// fp16 tensor-core flash attention, causal, dh=64 — byte-identical R13 winner.
// ===========================================================================
#define QP 36   // uint32 stride per Q/K row (32 data + 4 pad)
#define VP 72   // uint32 stride per V row-pair (64 data + 8 pad)
#define FL_SMEM ((64 * QP * 2 + 32 * VP) * 4)

__global__ __launch_bounds__(128, 4) void flash_mma_kernel()
{
    extern __shared__ uint32_t fsm[];
    uint32_t* Qs = fsm;                 // [64][QP]
    uint32_t* Ks = Qs + 64 * QP;        // [64][QP]
    uint32_t* Vs = Ks + 64 * QP;        // [32][VP]  row-pair packed

    const int tid  = threadIdx.x;
    const int wq   = tid >> 5;
    const int lane = tid & 31;
    const int g    = lane >> 2;
    const int tig  = lane & 3;
    const int qt   = gridDim.x - 1 - blockIdx.x;   // long CTAs first
    const int bh   = blockIdx.y;
    const int qi0  = qt * 64;

    const float* Qg = g_Q + (size_t)bh * N_ * DH_;
    const float* Kg = g_K + (size_t)bh * N_ * DH_;
    const float* Vg = g_V + (size_t)bh * N_ * DH_;

    const float qscale = 0.125f * 1.44269504088896340736f; // dh^-0.5 * log2(e)

#pragma unroll
    for (int u = 0; u < 8; u++) {
        int f  = tid + 128 * u;
        int r  = f >> 4;
        int dv = f & 15;
        float4 v = *(const float4*)(Qg + (size_t)(qi0 + r) * DH_ + dv * 4);
        *(uint2*)&Qs[r * QP + dv * 2] =
            make_uint2(h2pack(v.x * qscale, v.y * qscale),
                       h2pack(v.z * qscale, v.w * qscale));
    }

    float m0r = -1e30f, m1r = -1e30f;
    float l0r = 0.f, l1r = 0.f;
    float O[8][4];
#pragma unroll
    for (int j = 0; j < 8; j++)
#pragma unroll
        for (int e = 0; e < 4; e++) O[j][e] = 0.f;

    const int row0 = qi0 + wq * 16 + g;
    const int row1 = row0 + 8;

    for (int kt2 = 0; kt2 <= qt; kt2++) {
        const int kj0 = kt2 * 64;
        __syncthreads();

#pragma unroll
        for (int u = 0; u < 8; u++) {
            int f  = tid + 128 * u;
            int r  = f >> 4;
            int dv = f & 15;
            float4 kv = *(const float4*)(Kg + (size_t)(kj0 + r) * DH_ + dv * 4);
            *(uint2*)&Ks[r * QP + dv * 2] =
                make_uint2(h2pack(kv.x, kv.y), h2pack(kv.z, kv.w));
        }
#pragma unroll
        for (int u = 0; u < 4; u++) {
            int f  = tid + 128 * u;
            int m  = f >> 4;
            int ev = f & 15;
            float4 v0 = *(const float4*)(Vg + (size_t)(kj0 + 2 * m) * DH_ + ev * 4);
            float4 v1 = *(const float4*)(Vg + (size_t)(kj0 + 2 * m + 1) * DH_ + ev * 4);
            uint4 t;
            t.x = h2pack(v0.x, v1.x);
            t.y = h2pack(v0.y, v1.y);
            t.z = h2pack(v0.z, v1.z);
            t.w = h2pack(v0.w, v1.w);
            *(uint4*)&Vs[m * VP + ev * 4] = t;
        }
        __syncthreads();

        float S[8][4];
#pragma unroll
        for (int j = 0; j < 8; j++)
#pragma unroll
            for (int e = 0; e < 4; e++) S[j][e] = 0.f;

#pragma unroll
        for (int kb = 0; kb < 4; kb++) {
            const int ar = (wq * 16 + g) * QP + kb * 8 + tig;
            uint32_t a0 = Qs[ar];
            uint32_t a1 = Qs[ar + 8 * QP];
            uint32_t a2 = Qs[ar + 4];
            uint32_t a3 = Qs[ar + 8 * QP + 4];
#pragma unroll
            for (int j = 0; j < 8; j++) {
                const int br = (j * 8 + g) * QP + kb * 8 + tig;
                uint32_t b0 = Ks[br];
                uint32_t b1 = Ks[br + 4];
                mma_f16_16x8x16(S[j][0], S[j][1], S[j][2], S[j][3],
                                a0, a1, a2, a3, b0, b1);
            }
        }

        if (kt2 == qt) {
#pragma unroll
            for (int j = 0; j < 8; j++) {
                int c = kj0 + j * 8 + tig * 2;
                if (c     > row0) S[j][0] = -1e30f;
                if (c + 1 > row0) S[j][1] = -1e30f;
                if (c     > row1) S[j][2] = -1e30f;
                if (c + 1 > row1) S[j][3] = -1e30f;
            }
        }

        float rmax0 = -1e30f, rmax1 = -1e30f;
#pragma unroll
        for (int j = 0; j < 8; j++) {
            rmax0 = fmaxf(rmax0, fmaxf(S[j][0], S[j][1]));
            rmax1 = fmaxf(rmax1, fmaxf(S[j][2], S[j][3]));
        }
        rmax0 = fmaxf(rmax0, __shfl_xor_sync(0xffffffffu, rmax0, 1));
        rmax0 = fmaxf(rmax0, __shfl_xor_sync(0xffffffffu, rmax0, 2));
        rmax1 = fmaxf(rmax1, __shfl_xor_sync(0xffffffffu, rmax1, 1));
        rmax1 = fmaxf(rmax1, __shfl_xor_sync(0xffffffffu, rmax1, 2));

        float mn0 = fmaxf(m0r, rmax0);
        float mn1 = fmaxf(m1r, rmax1);
        float al0 = ex2f(m0r - mn0);
        float al1 = ex2f(m1r - mn1);
        m0r = mn0; m1r = mn1;

        float sum0 = 0.f, sum1 = 0.f;
        uint32_t ph[8][2];
#pragma unroll
        for (int j = 0; j < 8; j++) {
            float p0 = ex2f(S[j][0] - mn0);
            float p1 = ex2f(S[j][1] - mn0);
            float p2 = ex2f(S[j][2] - mn1);
            float p3 = ex2f(S[j][3] - mn1);
            sum0 += p0 + p1;
            sum1 += p2 + p3;
            ph[j][0] = h2pack(p0, p1);
            ph[j][1] = h2pack(p2, p3);
        }
        sum0 += __shfl_xor_sync(0xffffffffu, sum0, 1);
        sum0 += __shfl_xor_sync(0xffffffffu, sum0, 2);
        sum1 += __shfl_xor_sync(0xffffffffu, sum1, 1);
        sum1 += __shfl_xor_sync(0xffffffffu, sum1, 2);
        l0r = l0r * al0 + sum0;
        l1r = l1r * al1 + sum1;

#pragma unroll
        for (int j = 0; j < 8; j++) {
            O[j][0] *= al0; O[j][1] *= al0;
            O[j][2] *= al1; O[j][3] *= al1;
        }

#pragma unroll
        for (int kb = 0; kb < 4; kb++) {
            uint32_t a0 = ph[2 * kb][0];
            uint32_t a1 = ph[2 * kb][1];
            uint32_t a2 = ph[2 * kb + 1][0];
            uint32_t a3 = ph[2 * kb + 1][1];
#pragma unroll
            for (int j = 0; j < 8; j++) {
                uint32_t b0 = Vs[(kb * 8 + tig) * VP + j * 8 + g];
                uint32_t b1 = Vs[(kb * 8 + 4 + tig) * VP + j * 8 + g];
                mma_f16_16x8x16(O[j][0], O[j][1], O[j][2], O[j][3],
                                a0, a1, a2, a3, b0, b1);
            }
        }
    }

    const int b = bh >> 4;
    const int h = bh & 15;
    const float il0 = 1.f / l0r;
    const float il1 = 1.f / l1r;
    float* X0 = g_X + ((size_t)b * N_ + row0) * D_ + h * DH_;
    float* X1 = g_X + ((size_t)b * N_ + row1) * D_ + h * DH_;
#pragma unroll
    for (int j = 0; j < 8; j++) {
        int e = j * 8 + tig * 2;
        *(float2*)(X0 + e) = make_float2(O[j][0] * il0, O[j][1] * il0);
        *(float2*)(X1 + e) = make_float2(O[j][2] * il1, O[j][3] * il1);
    }
}

// ---------------------------------------------------------------------------
extern "C" void kernel_launch(void* const* d_in, const int* in_sizes, int n_in,
                              void* d_out, int out_size)
{
    const float* q  = (const float*)d_in[0];
    const float* k  = (const float*)d_in[1];
    const float* v  = (const float*)d_in[2];
    const float* Wq = (const float*)d_in[3];
    const float* bq = (const float*)d_in[4];
    const float* Wk = (const float*)d_in[5];
    const float* bk = (const float*)d_in[6];
    const float* Wv = (const float*)d_in[7];
    const float* bv = (const float*)d_in[8];
    const float* Wo = (const float*)d_in[9];
    float* out = (float*)d_out;

    cudaFuncSetAttribute(flash_mma_kernel, cudaFuncAttributeMaxDynamicSharedMemorySize,
                         FL_SMEM);

    // QKV projections: M=8192 -> 64 row-tiles, N=1024 -> 8 col-tiles, z = q/k/v
    dim3 gp(8, 64, 3);
    proj_qkv_mma<<<gp, 256>>>(q, k, v, Wq, bq, Wk, bk, Wv, bv);

    // Flash attention: 32 q-tiles x 64 (b,h) pairs
    dim3 gf(N_ / 64, B_ * H_);
    flash_mma_kernel<<<gf, 128, FL_SMEM>>>();

    // Output projection
    dim3 go(8, 64, 1);
    proj_out_mma<<<go, 256>>>(Wo, out);
}

// round 15
// speedup vs baseline: 1.0228x; 1.0228x over previous
#include <cuda_runtime.h>
#include <cuda_fp16.h>
#include <cstdint>
#include <math.h>

#define B_  4
#define N_  2048
#define D_  1024
#define H_  16
#define DH_ 64

// Scratch: projected Q/K/V in [B*H][N][dh] layout, attention output X in [B*N][D]
__device__ float g_Q[B_ * H_ * N_ * DH_];
__device__ float g_K[B_ * H_ * N_ * DH_];
__device__ float g_V[B_ * H_ * N_ * DH_];
__device__ float g_X[B_ * N_ * D_];

__device__ __forceinline__ float ex2f(float x) {
    float y;
    asm("ex2.approx.ftz.f32 %0, %1;" : "=f"(y) : "f"(x));
    return y;
}
// pack two f32 -> f16x2 (lo = x, hi = y), round-to-nearest
__device__ __forceinline__ uint32_t h2pack(float x, float y) {
    uint32_t r;
    asm("cvt.rn.f16x2.f32 %0, %1, %2;" : "=r"(r) : "f"(y), "f"(x));
    return r;
}

__device__ __forceinline__ void mma_f16_16x8x16(
    float& c0, float& c1, float& c2, float& c3,
    uint32_t a0, uint32_t a1, uint32_t a2, uint32_t a3,
    uint32_t b0, uint32_t b1)
{
    asm volatile(
        "mma.sync.aligned.m16n8k16.row.col.f32.f16.f16.f32 "
        "{%0,%1,%2,%3}, {%4,%5,%6,%7}, {%8,%9}, {%0,%1,%2,%3};"
        : "+f"(c0), "+f"(c1), "+f"(c2), "+f"(c3)
        : "r"(a0), "r"(a1), "r"(a2), "r"(a3), "r"(b0), "r"(b1));
}

// ===========================================================================
// fp16 mma.sync GEMM: C[M,1024] = A[M,1024] @ W^T (+bias f32), W [N][K].
// (byte-identical to the 680/535us R12/R13 winner: k-tile 32, KP=20)
// ===========================================================================
#define KP 20   // uint32 (half2) stride per row

template <bool OUT_HEADS, bool HAS_BIAS>
__device__ __forceinline__ void gemm_mma_body(
    const float* __restrict__ A, const float* __restrict__ W,
    const float* __restrict__ bias, float* __restrict__ out)
{
    __shared__ uint32_t As[128 * KP];
    __shared__ uint32_t Bs[128 * KP];

    const int tid  = threadIdx.x;
    const int wid  = tid >> 5;
    const int lane = tid & 31;
    const int g    = lane >> 2;
    const int tig  = lane & 3;
    const int wm   = wid & 3;
    const int wn   = wid >> 2;
    const int m0   = blockIdx.y * 128;
    const int n0   = blockIdx.x * 128;

    float c[2][8][4];
#pragma unroll
    for (int t = 0; t < 2; t++)
#pragma unroll
        for (int j = 0; j < 8; j++)
#pragma unroll
            for (int e = 0; e < 4; e++) c[t][j][e] = 0.f;

    const int ar0 = (wm * 32 + g) * KP + tig;
    const int br0 = (wn * 64 + g) * KP + tig;

    for (int kt = 0; kt < D_; kt += 32) {
#pragma unroll
        for (int u = 0; u < 4; u++) {
            int f    = tid + 256 * u;
            int j    = f & 7;
            int rblk = f >> 3;
            int row  = (rblk & ~7) | ((rblk & 1) << 2) | ((rblk & 7) >> 1);
            float4 av = __ldg((const float4*)(A + (size_t)(m0 + row) * D_ + kt + j * 4));
            *(uint2*)&As[row * KP + 2 * j] =
                make_uint2(h2pack(av.x, av.y), h2pack(av.z, av.w));
            float4 wv = __ldg((const float4*)(W + (size_t)(n0 + row) * D_ + kt + j * 4));
            *(uint2*)&Bs[row * KP + 2 * j] =
                make_uint2(h2pack(wv.x, wv.y), h2pack(wv.z, wv.w));
        }
        __syncthreads();

        uint32_t a[2][2][4];
        uint32_t b[2][8][2];

#pragma unroll
        for (int t = 0; t < 2; t++) {
            int r = ar0 + t * 16 * KP;
            a[0][t][0] = As[r];
            a[0][t][1] = As[r + 8 * KP];
            a[0][t][2] = As[r + 4];
            a[0][t][3] = As[r + 8 * KP + 4];
        }
#pragma unroll
        for (int j = 0; j < 8; j++) {
            int r = br0 + j * 8 * KP;
            b[0][j][0] = Bs[r];
            b[0][j][1] = Bs[r + 4];
        }

#pragma unroll
        for (int kb = 0; kb < 2; kb++) {
            const int cur = kb & 1;
            const int nxt = cur ^ 1;
            if (kb < 1) {
#pragma unroll
                for (int t = 0; t < 2; t++) {
                    int r = ar0 + t * 16 * KP + 8;
                    a[nxt][t][0] = As[r];
                    a[nxt][t][1] = As[r + 8 * KP];
                    a[nxt][t][2] = As[r + 4];
                    a[nxt][t][3] = As[r + 8 * KP + 4];
                }
#pragma unroll
                for (int j = 0; j < 8; j++) {
                    int r = br0 + j * 8 * KP + 8;
                    b[nxt][j][0] = Bs[r];
                    b[nxt][j][1] = Bs[r + 4];
                }
            }
#pragma unroll
            for (int t = 0; t < 2; t++)
#pragma unroll
                for (int j = 0; j < 8; j++)
                    mma_f16_16x8x16(c[t][j][0], c[t][j][1], c[t][j][2], c[t][j][3],
                                    a[cur][t][0], a[cur][t][1], a[cur][t][2], a[cur][t][3],
                                    b[cur][j][0], b[cur][j][1]);
        }
        __syncthreads();
    }

#pragma unroll
    for (int t = 0; t < 2; t++) {
        const int r0 = m0 + wm * 32 + t * 16 + g;
#pragma unroll
        for (int j = 0; j < 8; j++) {
            const int col = n0 + wn * 64 + j * 8 + tig * 2;
            float2 v0 = make_float2(c[t][j][0], c[t][j][1]);
            float2 v1 = make_float2(c[t][j][2], c[t][j][3]);
            if (HAS_BIAS) {
                float2 bv = *(const float2*)(bias + col);
                v0.x += bv.x; v0.y += bv.y;
                v1.x += bv.x; v1.y += bv.y;
            }
            if (OUT_HEADS) {
                const int h = col >> 6;
                const int di = col & 63;
                const int b0i = r0 >> 11, n0i = r0 & 2047;
                const int r1 = r0 + 8;
                const int b1i = r1 >> 11, n1i = r1 & 2047;
                *(float2*)(out + (((size_t)(b0i * H_ + h)) * N_ + n0i) * DH_ + di) = v0;
                *(float2*)(out + (((size_t)(b1i * H_ + h)) * N_ + n1i) * DH_ + di) = v1;
            } else {
                *(float2*)(out + (size_t)r0 * D_ + col) = v0;
                *(float2*)(out + (size_t)(r0 + 8) * D_ + col) = v1;
            }
        }
    }
}

__global__ __launch_bounds__(256, 2)
void proj_qkv_mma(const float* __restrict__ xq, const float* __restrict__ xk,
                  const float* __restrict__ xv,
                  const float* __restrict__ Wq, const float* __restrict__ bq,
                  const float* __restrict__ Wk, const float* __restrict__ bk,
                  const float* __restrict__ Wv, const float* __restrict__ bv)
{
    int z = blockIdx.z;
    const float* A = (z == 0) ? xq : (z == 1) ? xk : xv;
    const float* W = (z == 0) ? Wq : (z == 1) ? Wk : Wv;
    const float* b = (z == 0) ? bq : (z == 1) ? bk : bv;
    float* out = (z == 0) ? g_Q : (z == 1) ? g_K : g_V;
    gemm_mma_body<true, true>(A, W, b, out);
}

__global__ __launch_bounds__(256, 2)
void proj_out_mma(const float* __restrict__ Wo, float* __restrict__ out)
{
    gemm_mma_body<false, false>(g_X, Wo, nullptr, out);
}

// ===========================================================================
// fp16 tensor-core flash attention, causal, dh=64.
// CTA: 128 threads (4 warps), 64-query tile. m16n8k16 for QK^T and PV,
// shuffle-free P reshape (R13 structure), but K/V staged 128 KEYS per sync
// window (two 64-key compute passes per staged tile -> half the syncs).
// Smem: Q [64][36], K [128][36], V row-pair packed [64][72]  (46 KB).
// ===========================================================================
#define QP 36   // uint32 stride per Q/K row (32 data + 4 pad)
#define VP 72   // uint32 stride per V row-pair (64 data + 8 pad)
#define FL_SMEM ((64 * QP + 128 * QP + 64 * VP) * 4)

__global__ __launch_bounds__(128, 4) void flash_mma_kernel()
{
    extern __shared__ uint32_t fsm[];
    uint32_t* Qs = fsm;                 // [64][QP]
    uint32_t* Ks = Qs + 64 * QP;        // [128][QP]
    uint32_t* Vs = Ks + 128 * QP;       // [64][VP]  row-pair packed (128 rows)

    const int tid  = threadIdx.x;
    const int wq   = tid >> 5;
    const int lane = tid & 31;
    const int g    = lane >> 2;
    const int tig  = lane & 3;
    const int qt   = gridDim.x - 1 - blockIdx.x;   // long CTAs first
    const int bh   = blockIdx.y;
    const int qi0  = qt * 64;

    const float* Qg = g_Q + (size_t)bh * N_ * DH_;
    const float* Kg = g_K + (size_t)bh * N_ * DH_;
    const float* Vg = g_V + (size_t)bh * N_ * DH_;

    const float qscale = 0.125f * 1.44269504088896340736f; // dh^-0.5 * log2(e)

    // Stage Q (half2 along dh, pre-scaled): 64 rows x 16 float4 = 1024 slots
#pragma unroll
    for (int u = 0; u < 8; u++) {
        int f  = tid + 128 * u;
        int r  = f >> 4;
        int dv = f & 15;
        float4 v = *(const float4*)(Qg + (size_t)(qi0 + r) * DH_ + dv * 4);
        *(uint2*)&Qs[r * QP + dv * 2] =
            make_uint2(h2pack(v.x * qscale, v.y * qscale),
                       h2pack(v.z * qscale, v.w * qscale));
    }

    float m0r = -1e30f, m1r = -1e30f;
    float l0r = 0.f, l1r = 0.f;
    float O[8][4];
#pragma unroll
    for (int j = 0; j < 8; j++)
#pragma unroll
        for (int e = 0; e < 4; e++) O[j][e] = 0.f;

    const int row0 = qi0 + wq * 16 + g;
    const int row1 = row0 + 8;

    const int NT = qt / 2 + 1;            // 128-key staged tiles

    for (int T = 0; T < NT; T++) {
        const int kj0 = T * 128;
        __syncthreads();   // previous staged tile fully consumed

        // Stage K: 128 rows x 16 float4 = 2048 slots / 128 thr = 16 iters
#pragma unroll
        for (int u = 0; u < 16; u++) {
            int f  = tid + 128 * u;
            int r  = f >> 4;
            int dv = f & 15;
            float4 kv = *(const float4*)(Kg + (size_t)(kj0 + r) * DH_ + dv * 4);
            *(uint2*)&Ks[r * QP + dv * 2] =
                make_uint2(h2pack(kv.x, kv.y), h2pack(kv.z, kv.w));
        }
        // Stage V: 64 row-pairs x 16 float4-cols = 1024 slots = 8 iters
#pragma unroll
        for (int u = 0; u < 8; u++) {
            int f  = tid + 128 * u;
            int m  = f >> 4;            // row pair 0..63
            int ev = f & 15;
            float4 v0 = *(const float4*)(Vg + (size_t)(kj0 + 2 * m) * DH_ + ev * 4);
            float4 v1 = *(const float4*)(Vg + (size_t)(kj0 + 2 * m + 1) * DH_ + ev * 4);
            uint4 t;
            t.x = h2pack(v0.x, v1.x);
            t.y = h2pack(v0.y, v1.y);
            t.z = h2pack(v0.z, v1.z);
            t.w = h2pack(v0.w, v1.w);
            *(uint4*)&Vs[m * VP + ev * 4] = t;
        }
        __syncthreads();

        // Two 64-key compute passes from smem
#pragma unroll
        for (int hh = 0; hh < 2; hh++) {
            const int blk = 2 * T + hh;       // 64-key block index
            if (blk > qt) break;              // CTA-uniform
            const int kj = kj0 + 64 * hh;
            const uint32_t* Kh = Ks + (size_t)(64 * hh) * QP;
            const uint32_t* Vh = Vs + (size_t)(32 * hh) * VP;

            // ---- S = Q @ K^T ----
            float S[8][4];
#pragma unroll
            for (int j = 0; j < 8; j++)
#pragma unroll
                for (int e = 0; e < 4; e++) S[j][e] = 0.f;

#pragma unroll
            for (int kb = 0; kb < 4; kb++) {
                const int ar = (wq * 16 + g) * QP + kb * 8 + tig;
                uint32_t a0 = Qs[ar];
                uint32_t a1 = Qs[ar + 8 * QP];
                uint32_t a2 = Qs[ar + 4];
                uint32_t a3 = Qs[ar + 8 * QP + 4];
#pragma unroll
                for (int j = 0; j < 8; j++) {
                    const int br = (j * 8 + g) * QP + kb * 8 + tig;
                    uint32_t b0 = Kh[br];
                    uint32_t b1 = Kh[br + 4];
                    mma_f16_16x8x16(S[j][0], S[j][1], S[j][2], S[j][3],
                                    a0, a1, a2, a3, b0, b1);
                }
            }

            // ---- causal mask (diag block only) ----
            if (blk == qt) {
#pragma unroll
                for (int j = 0; j < 8; j++) {
                    int c = kj + j * 8 + tig * 2;
                    if (c     > row0) S[j][0] = -1e30f;
                    if (c + 1 > row0) S[j][1] = -1e30f;
                    if (c     > row1) S[j][2] = -1e30f;
                    if (c + 1 > row1) S[j][3] = -1e30f;
                }
            }

            // ---- online softmax (exp2 domain) ----
            float rmax0 = -1e30f, rmax1 = -1e30f;
#pragma unroll
            for (int j = 0; j < 8; j++) {
                rmax0 = fmaxf(rmax0, fmaxf(S[j][0], S[j][1]));
                rmax1 = fmaxf(rmax1, fmaxf(S[j][2], S[j][3]));
            }
            rmax0 = fmaxf(rmax0, __shfl_xor_sync(0xffffffffu, rmax0, 1));
            rmax0 = fmaxf(rmax0, __shfl_xor_sync(0xffffffffu, rmax0, 2));
            rmax1 = fmaxf(rmax1, __shfl_xor_sync(0xffffffffu, rmax1, 1));
            rmax1 = fmaxf(rmax1, __shfl_xor_sync(0xffffffffu, rmax1, 2));

            float mn0 = fmaxf(m0r, rmax0);
            float mn1 = fmaxf(m1r, rmax1);
            float al0 = ex2f(m0r - mn0);
            float al1 = ex2f(m1r - mn1);
            m0r = mn0; m1r = mn1;

            float sum0 = 0.f, sum1 = 0.f;
            uint32_t ph[8][2];
#pragma unroll
            for (int j = 0; j < 8; j++) {
                float p0 = ex2f(S[j][0] - mn0);
                float p1 = ex2f(S[j][1] - mn0);
                float p2 = ex2f(S[j][2] - mn1);
                float p3 = ex2f(S[j][3] - mn1);
                sum0 += p0 + p1;
                sum1 += p2 + p3;
                ph[j][0] = h2pack(p0, p1);
                ph[j][1] = h2pack(p2, p3);
            }
            sum0 += __shfl_xor_sync(0xffffffffu, sum0, 1);
            sum0 += __shfl_xor_sync(0xffffffffu, sum0, 2);
            sum1 += __shfl_xor_sync(0xffffffffu, sum1, 1);
            sum1 += __shfl_xor_sync(0xffffffffu, sum1, 2);
            l0r = l0r * al0 + sum0;
            l1r = l1r * al1 + sum1;

#pragma unroll
            for (int j = 0; j < 8; j++) {
                O[j][0] *= al0; O[j][1] *= al0;
                O[j][2] *= al1; O[j][3] *= al1;
            }

            // ---- O += P @ V (shuffle-free) ----
#pragma unroll
            for (int kb = 0; kb < 4; kb++) {
                uint32_t a0 = ph[2 * kb][0];
                uint32_t a1 = ph[2 * kb][1];
                uint32_t a2 = ph[2 * kb + 1][0];
                uint32_t a3 = ph[2 * kb + 1][1];
#pragma unroll
                for (int j = 0; j < 8; j++) {
                    uint32_t b0 = Vh[(kb * 8 + tig) * VP + j * 8 + g];
                    uint32_t b1 = Vh[(kb * 8 + 4 + tig) * VP + j * 8 + g];
                    mma_f16_16x8x16(O[j][0], O[j][1], O[j][2], O[j][3],
                                    a0, a1, a2, a3, b0, b1);
                }
            }
        }
    }

    // Epilogue: O /= l; write to g_X[b][n][h*64 + e]
    const int b = bh >> 4;
    const int h = bh & 15;
    const float il0 = 1.f / l0r;
    const float il1 = 1.f / l1r;
    float* X0 = g_X + ((size_t)b * N_ + row0) * D_ + h * DH_;
    float* X1 = g_X + ((size_t)b * N_ + row1) * D_ + h * DH_;
#pragma unroll
    for (int j = 0; j < 8; j++) {
        int e = j * 8 + tig * 2;
        *(float2*)(X0 + e) = make_float2(O[j][0] * il0, O[j][1] * il0);
        *(float2*)(X1 + e) = make_float2(O[j][2] * il1, O[j][3] * il1);
    }
}

// ---------------------------------------------------------------------------
extern "C" void kernel_launch(void* const* d_in, const int* in_sizes, int n_in,
                              void* d_out, int out_size)
{
    const float* q  = (const float*)d_in[0];
    const float* k  = (const float*)d_in[1];
    const float* v  = (const float*)d_in[2];
    const float* Wq = (const float*)d_in[3];
    const float* bq = (const float*)d_in[4];
    const float* Wk = (const float*)d_in[5];
    const float* bk = (const float*)d_in[6];
    const float* Wv = (const float*)d_in[7];
    const float* bv = (const float*)d_in[8];
    const float* Wo = (const float*)d_in[9];
    float* out = (float*)d_out;

    cudaFuncSetAttribute(flash_mma_kernel, cudaFuncAttributeMaxDynamicSharedMemorySize,
                         FL_SMEM);

    // QKV projections: M=8192 -> 64 row-tiles, N=1024 -> 8 col-tiles, z = q/k/v
    dim3 gp(8, 64, 3);
    proj_qkv_mma<<<gp, 256>>>(q, k, v, Wq, bq, Wk, bk, Wv, bv);

    // Flash attention: 32 q-tiles x 64 (b,h) pairs
    dim3 gf(N_ / 64, B_ * H_);
    flash_mma_kernel<<<gf, 128, FL_SMEM>>>();

    // Output projection
    dim3 go(8, 64, 1);
    proj_out_mma<<<go, 256>>>(Wo, out);
}

// round 16
// speedup vs baseline: 1.1235x; 1.0984x over previous
#include <cuda_runtime.h>
#include <cuda_fp16.h>
#include <cstdint>
#include <math.h>

#define B_  4
#define N_  2048
#define D_  1024
#define H_  16
#define DH_ 64

// Intermediates in fp16: projected Q (pre-scaled) / K / V in [B*H][N][dh],
// attention output X in [B*N][D]. Final output stays fp32.
__device__ __half g_Qh[B_ * H_ * N_ * DH_];
__device__ __half g_Kh[B_ * H_ * N_ * DH_];
__device__ __half g_Vh[B_ * H_ * N_ * DH_];
__device__ __half g_Xh[B_ * N_ * D_];
__device__ __half g_Wh[4][D_ * D_];      // pre-converted Wq,Wk,Wv,Wo

__device__ __forceinline__ float ex2f(float x) {
    float y;
    asm("ex2.approx.ftz.f32 %0, %1;" : "=f"(y) : "f"(x));
    return y;
}
// pack two f32 -> f16x2 (lo = x, hi = y), round-to-nearest
__device__ __forceinline__ uint32_t h2pack(float x, float y) {
    uint32_t r;
    asm("cvt.rn.f16x2.f32 %0, %1, %2;" : "=r"(r) : "f"(y), "f"(x));
    return r;
}
__device__ __forceinline__ uint32_t prmt(uint32_t a, uint32_t b, uint32_t sel) {
    uint32_t d;
    asm("prmt.b32 %0, %1, %2, %3;" : "=r"(d) : "r"(a), "r"(b), "r"(sel));
    return d;
}

__device__ __forceinline__ void mma_f16_16x8x16(
    float& c0, float& c1, float& c2, float& c3,
    uint32_t a0, uint32_t a1, uint32_t a2, uint32_t a3,
    uint32_t b0, uint32_t b1)
{
    asm volatile(
        "mma.sync.aligned.m16n8k16.row.col.f32.f16.f16.f32 "
        "{%0,%1,%2,%3}, {%4,%5,%6,%7}, {%8,%9}, {%0,%1,%2,%3};"
        : "+f"(c0), "+f"(c1), "+f"(c2), "+f"(c3)
        : "r"(a0), "r"(a1), "r"(a2), "r"(a3), "r"(b0), "r"(b1));
}

// ===========================================================================
// Pre-convert the 4 weight matrices to fp16 (one-time, ~8us).
// ===========================================================================
__global__ __launch_bounds__(256) void round_w(
    const float* __restrict__ wq, const float* __restrict__ wk,
    const float* __restrict__ wv, const float* __restrict__ wo)
{
    const int idx = blockIdx.x * 256 + threadIdx.x;     // float4 index
    const float* src = (blockIdx.y == 0) ? wq : (blockIdx.y == 1) ? wk
                     : (blockIdx.y == 2) ? wv : wo;
    float4 x = __ldg((const float4*)src + idx);
    uint2 t = make_uint2(h2pack(x.x, x.y), h2pack(x.z, x.w));
    *((uint2*)&g_Wh[blockIdx.y][0] + idx) = t;
}

// ===========================================================================
// fp16 mma.sync GEMM: C[M,1024] = A[M,1024] @ W^T (+bias f32).
// A either f32 (converted in producer, R12-proven path) or half (direct copy).
// W always half (pre-converted). Consumer loop = R12 winner, unchanged.
// Output either heads-scattered half (x oscale) or row-major f32.
// ===========================================================================
#define KP 20   // uint32 (half2) stride per row

template <bool HALF_A, bool OUT_HEADS, bool HAS_BIAS>
__device__ __forceinline__ void gemm_mma_body(
    const float* __restrict__ Af, const __half* __restrict__ Ah,
    const __half* __restrict__ Wh,
    const float* __restrict__ bias,
    float* __restrict__ outf, __half* __restrict__ outh, float oscale)
{
    __shared__ uint32_t As[128 * KP];
    __shared__ uint32_t Bs[128 * KP];

    const int tid  = threadIdx.x;
    const int wid  = tid >> 5;
    const int lane = tid & 31;
    const int g    = lane >> 2;
    const int tig  = lane & 3;
    const int wm   = wid & 3;
    const int wn   = wid >> 2;
    const int m0   = blockIdx.y * 128;
    const int n0   = blockIdx.x * 128;

    float c[2][8][4];
#pragma unroll
    for (int t = 0; t < 2; t++)
#pragma unroll
        for (int j = 0; j < 8; j++)
#pragma unroll
            for (int e = 0; e < 4; e++) c[t][j][e] = 0.f;

    const int ar0 = (wm * 32 + g) * KP + tig;
    const int br0 = (wn * 64 + g) * KP + tig;

    for (int kt = 0; kt < D_; kt += 32) {
        // ---- Producer: A tile ----
        if (HALF_A) {
            // 128 rows x 4 16B-chunks = 512 slots, 2/thread, direct copy
#pragma unroll
            for (int u = 0; u < 2; u++) {
                int f   = tid + 256 * u;
                int row = f >> 2;
                int cc  = f & 3;
                uint4 v = *(const uint4*)(Ah + (size_t)(m0 + row) * D_ + kt + cc * 8);
                *(uint4*)&As[row * KP + cc * 4] = v;
            }
        } else {
            // R12-proven f32 path with row permutation (STS.64 bank coverage)
#pragma unroll
            for (int u = 0; u < 4; u++) {
                int f    = tid + 256 * u;
                int j    = f & 7;
                int rblk = f >> 3;
                int row  = (rblk & ~7) | ((rblk & 1) << 2) | ((rblk & 7) >> 1);
                float4 av = __ldg((const float4*)(Af + (size_t)(m0 + row) * D_ + kt + j * 4));
                *(uint2*)&As[row * KP + 2 * j] =
                    make_uint2(h2pack(av.x, av.y), h2pack(av.z, av.w));
            }
        }
        // ---- Producer: W tile (half, direct copy) ----
#pragma unroll
        for (int u = 0; u < 2; u++) {
            int f   = tid + 256 * u;
            int row = f >> 2;
            int cc  = f & 3;
            uint4 v = *(const uint4*)(Wh + (size_t)(n0 + row) * D_ + kt + cc * 8);
            *(uint4*)&Bs[row * KP + cc * 4] = v;
        }
        __syncthreads();

        // ---- Consumer (R12 winner, unchanged) ----
        uint32_t a[2][2][4];
        uint32_t b[2][8][2];

#pragma unroll
        for (int t = 0; t < 2; t++) {
            int r = ar0 + t * 16 * KP;
            a[0][t][0] = As[r];
            a[0][t][1] = As[r + 8 * KP];
            a[0][t][2] = As[r + 4];
            a[0][t][3] = As[r + 8 * KP + 4];
        }
#pragma unroll
        for (int j = 0; j < 8; j++) {
            int r = br0 + j * 8 * KP;
            b[0][j][0] = Bs[r];
            b[0][j][1] = Bs[r + 4];
        }

#pragma unroll
        for (int kb = 0; kb < 2; kb++) {
            const int cur = kb & 1;
            const int nxt = cur ^ 1;
            if (kb < 1) {
#pragma unroll
                for (int t = 0; t < 2; t++) {
                    int r = ar0 + t * 16 * KP + 8;
                    a[nxt][t][0] = As[r];
                    a[nxt][t][1] = As[r + 8 * KP];
                    a[nxt][t][2] = As[r + 4];
                    a[nxt][t][3] = As[r + 8 * KP + 4];
                }
#pragma unroll
                for (int j = 0; j < 8; j++) {
                    int r = br0 + j * 8 * KP + 8;
                    b[nxt][j][0] = Bs[r];
                    b[nxt][j][1] = Bs[r + 4];
                }
            }
#pragma unroll
            for (int t = 0; t < 2; t++)
#pragma unroll
                for (int j = 0; j < 8; j++)
                    mma_f16_16x8x16(c[t][j][0], c[t][j][1], c[t][j][2], c[t][j][3],
                                    a[cur][t][0], a[cur][t][1], a[cur][t][2], a[cur][t][3],
                                    b[cur][j][0], b[cur][j][1]);
        }
        __syncthreads();
    }

    // ---- Epilogue ----
#pragma unroll
    for (int t = 0; t < 2; t++) {
        const int r0 = m0 + wm * 32 + t * 16 + g;
#pragma unroll
        for (int j = 0; j < 8; j++) {
            const int col = n0 + wn * 64 + j * 8 + tig * 2;
            float2 v0 = make_float2(c[t][j][0], c[t][j][1]);
            float2 v1 = make_float2(c[t][j][2], c[t][j][3]);
            if (HAS_BIAS) {
                float2 bv = *(const float2*)(bias + col);
                v0.x += bv.x; v0.y += bv.y;
                v1.x += bv.x; v1.y += bv.y;
            }
            if (OUT_HEADS) {
                const int h = col >> 6;
                const int di = col & 63;
                const int b0i = r0 >> 11, n0i = r0 & 2047;
                const int r1 = r0 + 8;
                const int b1i = r1 >> 11, n1i = r1 & 2047;
                *(uint32_t*)(outh + (((size_t)(b0i * H_ + h)) * N_ + n0i) * DH_ + di) =
                    h2pack(v0.x * oscale, v0.y * oscale);
                *(uint32_t*)(outh + (((size_t)(b1i * H_ + h)) * N_ + n1i) * DH_ + di) =
                    h2pack(v1.x * oscale, v1.y * oscale);
            } else {
                *(float2*)(outf + (size_t)r0 * D_ + col) = v0;
                *(float2*)(outf + (size_t)(r0 + 8) * D_ + col) = v1;
            }
        }
    }
}

__global__ __launch_bounds__(256, 2)
void proj_qkv_mma(const float* __restrict__ xq, const float* __restrict__ xk,
                  const float* __restrict__ xv,
                  const float* __restrict__ bq, const float* __restrict__ bk,
                  const float* __restrict__ bv)
{
    int z = blockIdx.z;
    const float* A = (z == 0) ? xq : (z == 1) ? xk : xv;
    const float* b = (z == 0) ? bq : (z == 1) ? bk : bv;
    __half* out = (z == 0) ? g_Qh : (z == 1) ? g_Kh : g_Vh;
    const float qscale = 0.125f * 1.44269504088896340736f;
    float os = (z == 0) ? qscale : 1.0f;
    gemm_mma_body<false, true, true>(A, nullptr, &g_Wh[z][0], b, nullptr, out, os);
}

__global__ __launch_bounds__(256, 2)
void proj_out_mma(float* __restrict__ out)
{
    gemm_mma_body<true, false, false>(nullptr, g_Xh, &g_Wh[3][0], nullptr,
                                      out, nullptr, 1.0f);
}

// ===========================================================================
// fp16 tensor-core flash attention, causal, dh=64. R13 compute core.
// Staging is copy-only from half intermediates (Q pre-scaled at projection).
// Smem: Q [64][36], K [64][36], V row-pair packed [32][72].
// ===========================================================================
#define QP 36   // uint32 stride per Q/K row (32 data + 4 pad)
#define VP 72   // uint32 stride per V row-pair (64 data + 8 pad)
#define FL_SMEM ((64 * QP * 2 + 32 * VP) * 4)

__global__ __launch_bounds__(128, 4) void flash_mma_kernel()
{
    extern __shared__ uint32_t fsm[];
    uint32_t* Qs = fsm;                 // [64][QP]
    uint32_t* Ks = Qs + 64 * QP;        // [64][QP]
    uint32_t* Vs = Ks + 64 * QP;        // [32][VP]  row-pair packed

    const int tid  = threadIdx.x;
    const int wq   = tid >> 5;
    const int lane = tid & 31;
    const int g    = lane >> 2;
    const int tig  = lane & 3;
    const int qt   = gridDim.x - 1 - blockIdx.x;   // long CTAs first
    const int bh   = blockIdx.y;
    const int qi0  = qt * 64;

    const __half* Qg = g_Qh + (size_t)bh * N_ * DH_;
    const __half* Kg = g_Kh + (size_t)bh * N_ * DH_;
    const __half* Vg = g_Vh + (size_t)bh * N_ * DH_;

    // Stage Q (already scaled, half): 64 rows x 8 uint4 = 512 slots, 4/thread
#pragma unroll
    for (int u = 0; u < 4; u++) {
        int f = tid + 128 * u;
        int r = f >> 3;
        int c = f & 7;
        uint4 v = *(const uint4*)(Qg + (size_t)(qi0 + r) * DH_ + c * 8);
        *(uint4*)&Qs[r * QP + c * 4] = v;
    }

    float m0r = -1e30f, m1r = -1e30f;
    float l0r = 0.f, l1r = 0.f;
    float O[8][4];
#pragma unroll
    for (int j = 0; j < 8; j++)
#pragma unroll
        for (int e = 0; e < 4; e++) O[j][e] = 0.f;

    const int row0 = qi0 + wq * 16 + g;
    const int row1 = row0 + 8;

    for (int kt2 = 0; kt2 <= qt; kt2++) {
        const int kj0 = kt2 * 64;
        __syncthreads();   // previous iteration done with Ks/Vs

        // Stage K: copy-only, 512 uint4 slots, 4/thread
#pragma unroll
        for (int u = 0; u < 4; u++) {
            int f = tid + 128 * u;
            int r = f >> 3;
            int c = f & 7;
            uint4 v = *(const uint4*)(Kg + (size_t)(kj0 + r) * DH_ + c * 8);
            *(uint4*)&Ks[r * QP + c * 4] = v;
        }
        // Stage V row-pair interleaved via PRMT: 32 pairs x 16 col-chunks
#pragma unroll
        for (int u = 0; u < 4; u++) {
            int f  = tid + 128 * u;
            int m  = f >> 4;            // row pair 0..31
            int ev = f & 15;            // 4-col chunk
            uint2 a = *(const uint2*)(Vg + (size_t)(kj0 + 2 * m) * DH_ + ev * 4);
            uint2 b = *(const uint2*)(Vg + (size_t)(kj0 + 2 * m + 1) * DH_ + ev * 4);
            uint4 t;
            t.x = prmt(a.x, b.x, 0x5410);
            t.y = prmt(a.x, b.x, 0x7632);
            t.z = prmt(a.y, b.y, 0x5410);
            t.w = prmt(a.y, b.y, 0x7632);
            *(uint4*)&Vs[m * VP + ev * 4] = t;
        }
        __syncthreads();

        // ---- S = Q @ K^T ----
        float S[8][4];
#pragma unroll
        for (int j = 0; j < 8; j++)
#pragma unroll
            for (int e = 0; e < 4; e++) S[j][e] = 0.f;

#pragma unroll
        for (int kb = 0; kb < 4; kb++) {
            const int ar = (wq * 16 + g) * QP + kb * 8 + tig;
            uint32_t a0 = Qs[ar];
            uint32_t a1 = Qs[ar + 8 * QP];
            uint32_t a2 = Qs[ar + 4];
            uint32_t a3 = Qs[ar + 8 * QP + 4];
#pragma unroll
            for (int j = 0; j < 8; j++) {
                const int br = (j * 8 + g) * QP + kb * 8 + tig;
                uint32_t b0 = Ks[br];
                uint32_t b1 = Ks[br + 4];
                mma_f16_16x8x16(S[j][0], S[j][1], S[j][2], S[j][3],
                                a0, a1, a2, a3, b0, b1);
            }
        }

        // ---- causal mask (diag tile only) ----
        if (kt2 == qt) {
#pragma unroll
            for (int j = 0; j < 8; j++) {
                int c = kj0 + j * 8 + tig * 2;
                if (c     > row0) S[j][0] = -1e30f;
                if (c + 1 > row0) S[j][1] = -1e30f;
                if (c     > row1) S[j][2] = -1e30f;
                if (c + 1 > row1) S[j][3] = -1e30f;
            }
        }

        // ---- online softmax (exp2 domain) ----
        float rmax0 = -1e30f, rmax1 = -1e30f;
#pragma unroll
        for (int j = 0; j < 8; j++) {
            rmax0 = fmaxf(rmax0, fmaxf(S[j][0], S[j][1]));
            rmax1 = fmaxf(rmax1, fmaxf(S[j][2], S[j][3]));
        }
        rmax0 = fmaxf(rmax0, __shfl_xor_sync(0xffffffffu, rmax0, 1));
        rmax0 = fmaxf(rmax0, __shfl_xor_sync(0xffffffffu, rmax0, 2));
        rmax1 = fmaxf(rmax1, __shfl_xor_sync(0xffffffffu, rmax1, 1));
        rmax1 = fmaxf(rmax1, __shfl_xor_sync(0xffffffffu, rmax1, 2));

        float mn0 = fmaxf(m0r, rmax0);
        float mn1 = fmaxf(m1r, rmax1);
        float al0 = ex2f(m0r - mn0);
        float al1 = ex2f(m1r - mn1);
        m0r = mn0; m1r = mn1;

        float sum0 = 0.f, sum1 = 0.f;
        uint32_t ph[8][2];
#pragma unroll
        for (int j = 0; j < 8; j++) {
            float p0 = ex2f(S[j][0] - mn0);
            float p1 = ex2f(S[j][1] - mn0);
            float p2 = ex2f(S[j][2] - mn1);
            float p3 = ex2f(S[j][3] - mn1);
            sum0 += p0 + p1;
            sum1 += p2 + p3;
            ph[j][0] = h2pack(p0, p1);
            ph[j][1] = h2pack(p2, p3);
        }
        sum0 += __shfl_xor_sync(0xffffffffu, sum0, 1);
        sum0 += __shfl_xor_sync(0xffffffffu, sum0, 2);
        sum1 += __shfl_xor_sync(0xffffffffu, sum1, 1);
        sum1 += __shfl_xor_sync(0xffffffffu, sum1, 2);
        l0r = l0r * al0 + sum0;
        l1r = l1r * al1 + sum1;

#pragma unroll
        for (int j = 0; j < 8; j++) {
            O[j][0] *= al0; O[j][1] *= al0;
            O[j][2] *= al1; O[j][3] *= al1;
        }

        // ---- O += P @ V (shuffle-free) ----
#pragma unroll
        for (int kb = 0; kb < 4; kb++) {
            uint32_t a0 = ph[2 * kb][0];
            uint32_t a1 = ph[2 * kb][1];
            uint32_t a2 = ph[2 * kb + 1][0];
            uint32_t a3 = ph[2 * kb + 1][1];
#pragma unroll
            for (int j = 0; j < 8; j++) {
                uint32_t b0 = Vs[(kb * 8 + tig) * VP + j * 8 + g];
                uint32_t b1 = Vs[(kb * 8 + 4 + tig) * VP + j * 8 + g];
                mma_f16_16x8x16(O[j][0], O[j][1], O[j][2], O[j][3],
                                a0, a1, a2, a3, b0, b1);
            }
        }
    }

    // Epilogue: O /= l; write half g_Xh[b][n][h*64 + e]
    const int b = bh >> 4;
    const int h = bh & 15;
    const float il0 = 1.f / l0r;
    const float il1 = 1.f / l1r;
    __half* X0 = g_Xh + ((size_t)b * N_ + row0) * D_ + h * DH_;
    __half* X1 = g_Xh + ((size_t)b * N_ + row1) * D_ + h * DH_;
#pragma unroll
    for (int j = 0; j < 8; j++) {
        int e = j * 8 + tig * 2;
        *(uint32_t*)(X0 + e) = h2pack(O[j][0] * il0, O[j][1] * il0);
        *(uint32_t*)(X1 + e) = h2pack(O[j][2] * il1, O[j][3] * il1);
    }
}

// ---------------------------------------------------------------------------
extern "C" void kernel_launch(void* const* d_in, const int* in_sizes, int n_in,
                              void* d_out, int out_size)
{
    const float* q  = (const float*)d_in[0];
    const float* k  = (const float*)d_in[1];
    const float* v  = (const float*)d_in[2];
    const float* Wq = (const float*)d_in[3];
    const float* bq = (const float*)d_in[4];
    const float* Wk = (const float*)d_in[5];
    const float* bk = (const float*)d_in[6];
    const float* Wv = (const float*)d_in[7];
    const float* bv = (const float*)d_in[8];
    const float* Wo = (const float*)d_in[9];
    float* out = (float*)d_out;

    cudaFuncSetAttribute(flash_mma_kernel, cudaFuncAttributeMaxDynamicSharedMemorySize,
                         FL_SMEM);

    // Pre-convert weights to fp16 (1M float4 per matrix)
    dim3 gw(D_ * D_ / 4 / 256, 4);
    round_w<<<gw, 256>>>(Wq, Wk, Wv, Wo);

    // QKV projections: M=8192 -> 64 row-tiles, N=1024 -> 8 col-tiles, z = q/k/v
    dim3 gp(8, 64, 3);
    proj_qkv_mma<<<gp, 256>>>(q, k, v, bq, bk, bv);

    // Flash attention: 32 q-tiles x 64 (b,h) pairs
    dim3 gf(N_ / 64, B_ * H_);
    flash_mma_kernel<<<gf, 128, FL_SMEM>>>();

    // Output projection
    dim3 go(8, 64, 1);
    proj_out_mma<<<go, 256>>>(out);
}